// round 1
// baseline (speedup 1.0000x reference)
#include <cuda_runtime.h>
#include <math.h>

#define NB 32
#define NN 512
#define DD 256
#define INV_EPS 10.0f
#define EPSF 0.1f
#define TINYF 1e-16f
#define MARG (1.0f/512.0f)
#define ITERS 15

// ---------------- scratch (static __device__; no allocations) ----------------
static __device__ float g_xn[(size_t)NB*NN*DD];   // 16 MB normalized x
static __device__ float g_yn[(size_t)NB*NN*DD];   // 16 MB normalized y
static __device__ float g_E [(size_t)NB*NN*NN];   // 32 MB  E = exp(-C/eps)
static __device__ float g_u [NB*NN];
static __device__ float g_v [NB*NN];
static __device__ float g_p [NB*NN];              // exp(alpha/eps)
static __device__ float g_q [NB*NN];              // exp(beta/eps)
static __device__ float g_cpart[NB*16];           // per-(batch,chunk) cost partials

// ---------------- 1) row-normalize x and y (cosine denominator) --------------
// one warp per 256-float row; 2*NB*NN = 32768 rows total
__global__ void norm_kernel(const float* __restrict__ x, const float* __restrict__ y) {
    int gw   = (blockIdx.x * blockDim.x + threadIdx.x) >> 5;
    int lane = threadIdx.x & 31;
    const float* src; float* dst; int row;
    if (gw < NB*NN) { src = x; dst = g_xn; row = gw; }
    else            { src = y; dst = g_yn; row = gw - NB*NN; }
    const float4* s4 = (const float4*)(src + (size_t)row * DD);
    float4 a = s4[lane];
    float4 b = s4[lane + 32];
    float ss = a.x*a.x + a.y*a.y + a.z*a.z + a.w*a.w
             + b.x*b.x + b.y*b.y + b.z*b.z + b.w*b.w;
    #pragma unroll
    for (int o = 16; o; o >>= 1) ss += __shfl_xor_sync(0xffffffffu, ss, o);
    float r = rsqrtf(ss);          // norms ~16 here; the 1e-8 clamp never binds
    a.x*=r; a.y*=r; a.z*=r; a.w*=r;
    b.x*=r; b.y*=r; b.z*=r; b.w*=r;
    float4* d4 = (float4*)(dst + (size_t)row * DD);
    d4[lane]      = a;
    d4[lane + 32] = b;
}

// ---------------- 2) batched GEMM: C = 1 - xn*yn^T ; E = exp(-10*C) ----------
// 64x64 tile, 256 threads, 4x4 per thread, K-slab 16
__global__ void gemm_kernel(float* __restrict__ Cout) {
    __shared__ float As[16][64];
    __shared__ float Bs[16][64];
    int b  = blockIdx.z;
    int m0 = blockIdx.y * 64, n0 = blockIdx.x * 64;
    const float* A = g_xn + (size_t)b * NN * DD;
    const float* B = g_yn + (size_t)b * NN * DD;
    int t  = threadIdx.x;
    int tx = t & 15, ty = t >> 4;
    int lr = t >> 2, lk = (t & 3) << 2;
    float acc[4][4] = {};
    for (int k0 = 0; k0 < DD; k0 += 16) {
        float4 av = *(const float4*)(A + (size_t)(m0 + lr) * DD + k0 + lk);
        float4 bv = *(const float4*)(B + (size_t)(n0 + lr) * DD + k0 + lk);
        As[lk+0][lr] = av.x; As[lk+1][lr] = av.y; As[lk+2][lr] = av.z; As[lk+3][lr] = av.w;
        Bs[lk+0][lr] = bv.x; Bs[lk+1][lr] = bv.y; Bs[lk+2][lr] = bv.z; Bs[lk+3][lr] = bv.w;
        __syncthreads();
        #pragma unroll
        for (int k = 0; k < 16; k++) {
            float4 a  = *(const float4*)&As[k][ty << 2];
            float4 bb = *(const float4*)&Bs[k][tx << 2];
            acc[0][0] += a.x*bb.x; acc[0][1] += a.x*bb.y; acc[0][2] += a.x*bb.z; acc[0][3] += a.x*bb.w;
            acc[1][0] += a.y*bb.x; acc[1][1] += a.y*bb.y; acc[1][2] += a.y*bb.z; acc[1][3] += a.y*bb.w;
            acc[2][0] += a.z*bb.x; acc[2][1] += a.z*bb.y; acc[2][2] += a.z*bb.z; acc[2][3] += a.z*bb.w;
            acc[3][0] += a.w*bb.x; acc[3][1] += a.w*bb.y; acc[3][2] += a.w*bb.z; acc[3][3] += a.w*bb.w;
        }
        __syncthreads();
    }
    size_t base = (size_t)b * NN * NN;
    #pragma unroll
    for (int i = 0; i < 4; i++) {
        int row = m0 + (ty << 2) + i;
        #pragma unroll
        for (int j = 0; j < 4; j++) {
            int col = n0 + (tx << 2) + j;
            float c = 1.0f - acc[i][j];
            Cout[base + (size_t)row * NN + col] = c;
            g_E [base + (size_t)row * NN + col] = __expf(-INV_EPS * c);
        }
    }
}

// ---------------- 3) init u=v=p=q=1 ------------------------------------------
__global__ void init_kernel() {
    int i = blockIdx.x * blockDim.x + threadIdx.x;
    if (i < NB*NN) { g_u[i] = 1.f; g_v[i] = 1.f; g_p[i] = 1.f; g_q[i] = 1.f; }
}

// ---------------- 4a) row half-step: u_i = a/(p_i * sum_j E_ij q_j v_j + TINY)
// then p_i *= u_i  (== s_i needed by the column half-step)
// grid = NB*16, block 256 (8 warps), each warp 4 rows, vectorized row dot
__global__ void row_kernel() {
    int b     = blockIdx.x >> 4;
    int chunk = blockIdx.x & 15;
    __shared__ float wsh[NN];
    int t = threadIdx.x;
    for (int j = t; j < NN; j += 256) wsh[j] = g_q[b*NN + j] * g_v[b*NN + j];
    __syncthreads();
    int warp = t >> 5, lane = t & 31;
    size_t base = (size_t)b * NN * NN;
    #pragma unroll
    for (int r = 0; r < 4; r++) {
        int row = chunk * 32 + warp * 4 + r;
        const float4* E4 = (const float4*)(g_E + base + (size_t)row * NN);
        const float4* W4 = (const float4*)wsh;
        float acc = 0.f;
        #pragma unroll
        for (int c = 0; c < 4; c++) {
            float4 e = E4[lane * 4 + c];
            float4 w = W4[lane * 4 + c];
            acc += e.x*w.x + e.y*w.y + e.z*w.z + e.w*w.w;
        }
        #pragma unroll
        for (int o = 16; o; o >>= 1) acc += __shfl_xor_sync(0xffffffffu, acc, o);
        if (lane == 0) {
            float p = g_p[b*NN + row];
            float u = MARG / (p * acc + TINYF);
            g_u[b*NN + row] = u;
            g_p[b*NN + row] = p * u;     // new p == p_old*u, used by col pass
        }
    }
}

// ---------------- 4b) col half-step: v_j = b/(q_j * sum_i E_ij p_i + TINY)
// (g_p already holds p_old*u_new); then q_j *= v_j
// grid = NB*4, block 256: 128 columns/block, each column split across 2 threads
__global__ void col_kernel() {
    int b     = blockIdx.x >> 2;
    int chunk = blockIdx.x & 3;
    __shared__ float psh[NN];
    __shared__ float part[128];
    int t = threadIdx.x;
    for (int i = t; i < NN; i += 256) psh[i] = g_p[b*NN + i];
    __syncthreads();
    int col  = chunk * 128 + (t & 127);
    int half = t >> 7;
    const float* Eb = g_E + (size_t)b * NN * NN + col;
    float acc = 0.f;
    int i0 = half * 256;
    #pragma unroll 16
    for (int i = 0; i < 256; i++) {
        acc += Eb[(size_t)(i0 + i) * NN] * psh[i0 + i];
    }
    if (half) part[t & 127] = acc;
    __syncthreads();
    if (!half) {
        float tot = acc + part[t];
        float q = g_q[b*NN + col];
        float v = MARG / (q * tot + TINYF);
        g_v[b*NN + col] = v;
        g_q[b*NN + col] = q * v;
    }
}

// ---------------- 5) pi = E * (u_i p_i) * (v_j q_j); cost partials -----------
__global__ void final_kernel(float* __restrict__ pi, const float* __restrict__ C) {
    int b     = blockIdx.x >> 4;
    int chunk = blockIdx.x & 15;
    __shared__ float svs[NN];
    __shared__ float red[256];
    int t = threadIdx.x;
    for (int j = t; j < NN; j += 256) svs[j] = g_v[b*NN + j] * g_q[b*NN + j];
    __syncthreads();
    int warp = t >> 5, lane = t & 31;
    size_t base = (size_t)b * NN * NN;
    float csum = 0.f;
    #pragma unroll
    for (int r = 0; r < 4; r++) {
        int row = chunk * 32 + warp * 4 + r;
        float su = g_u[b*NN + row] * g_p[b*NN + row];
        const float4* E4 = (const float4*)(g_E + base + (size_t)row * NN);
        const float4* C4 = (const float4*)(C   + base + (size_t)row * NN);
        float4*       P4 = (float4*)      (pi  + base + (size_t)row * NN);
        const float4* S4 = (const float4*)svs;
        #pragma unroll
        for (int c = 0; c < 4; c++) {
            int idx = lane * 4 + c;
            float4 e  = E4[idx];
            float4 s  = S4[idx];
            float4 cc = C4[idx];
            float4 pv;
            pv.x = e.x * su * s.x;
            pv.y = e.y * su * s.y;
            pv.z = e.z * su * s.z;
            pv.w = e.w * su * s.w;
            csum += pv.x*cc.x + pv.y*cc.y + pv.z*cc.z + pv.w*cc.w;
            P4[idx] = pv;
        }
    }
    red[t] = csum;
    __syncthreads();
    for (int o = 128; o; o >>= 1) {
        if (t < o) red[t] += red[t + o];
        __syncthreads();
    }
    if (t == 0) g_cpart[b * 16 + chunk] = red[0];
}

// ---------------- 6) reduce cost partials ------------------------------------
__global__ void cost_kernel(float* __restrict__ cost) {
    int b = threadIdx.x;
    if (b < NB) {
        float s = 0.f;
        #pragma unroll
        for (int c = 0; c < 16; c++) s += g_cpart[b * 16 + c];
        cost[b] = s;
    }
}

// ---------------- launch ------------------------------------------------------
extern "C" void kernel_launch(void* const* d_in, const int* in_sizes, int n_in,
                              void* d_out, int out_size) {
    const float* x = (const float*)d_in[0];
    const float* y = (const float*)d_in[1];
    float* out  = (float*)d_out;
    // output layout: cost[NB], pi[NB*NN*NN], C[NB*NN*NN] (tuple flatten order)
    float* cost = out;
    float* pi   = out + NB;
    float* C    = out + NB + (size_t)NB * NN * NN;

    norm_kernel<<<4096, 256>>>(x, y);
    gemm_kernel<<<dim3(8, 8, NB), 256>>>(C);
    init_kernel<<<(NB * NN + 255) / 256, 256>>>();
    for (int it = 0; it < ITERS; it++) {
        row_kernel<<<NB * 16, 256>>>();
        col_kernel<<<NB * 4, 256>>>();
    }
    final_kernel<<<NB * 16, 256>>>(pi, C);
    cost_kernel<<<1, 32>>>(cost);
}

// round 2
// speedup vs baseline: 1.8498x; 1.8498x over previous
#include <cuda_runtime.h>
#include <math.h>

#define NB 32
#define NN 512
#define DD 256
#define INV_EPS 10.0f
#define TINYF 1e-16f
#define MARG (1.0f/512.0f)
#define ITERS 15

// ---------------- scratch (static __device__; no allocations) ----------------
static __device__ float g_xn[(size_t)NB*NN*DD];        // 16 MB normalized x
static __device__ float g_yn[(size_t)NB*NN*DD];        // 16 MB normalized y
static __device__ float g_E [(size_t)NB*NN*NN];        // 32 MB  E = exp(-C/eps)
static __device__ float g_u [NB*NN];
static __device__ float g_v [NB*NN];
static __device__ float g_p [NB*NN];                   // exp(alpha/eps) (absorbed u)
static __device__ float g_q [NB*NN];                   // exp(beta/eps)  (absorbed v)
static __device__ float g_w [NB*NN];                   // w_j = q_j * v_j  (row-pass vector)
static __device__ float g_colpart[(size_t)NB*16*NN];   // per-(batch,block) col partials, 1MB
static __device__ float g_cpart[NB*16];                // cost partials

// ---------------- 1) row-normalize x and y -----------------------------------
__global__ void norm_kernel(const float* __restrict__ x, const float* __restrict__ y) {
    int gw   = (blockIdx.x * blockDim.x + threadIdx.x) >> 5;
    int lane = threadIdx.x & 31;
    const float* src; float* dst; int row;
    if (gw < NB*NN) { src = x; dst = g_xn; row = gw; }
    else            { src = y; dst = g_yn; row = gw - NB*NN; }
    const float4* s4 = (const float4*)(src + (size_t)row * DD);
    float4 a = s4[lane];
    float4 b = s4[lane + 32];
    float ss = a.x*a.x + a.y*a.y + a.z*a.z + a.w*a.w
             + b.x*b.x + b.y*b.y + b.z*b.z + b.w*b.w;
    #pragma unroll
    for (int o = 16; o; o >>= 1) ss += __shfl_xor_sync(0xffffffffu, ss, o);
    float r = rsqrtf(ss);
    a.x*=r; a.y*=r; a.z*=r; a.w*=r;
    b.x*=r; b.y*=r; b.z*=r; b.w*=r;
    float4* d4 = (float4*)(dst + (size_t)row * DD);
    d4[lane]      = a;
    d4[lane + 32] = b;
}

// ---------------- 2) batched GEMM: C = 1 - xn*yn^T ; E = exp(-10*C) ----------
__global__ void gemm_kernel(float* __restrict__ Cout) {
    __shared__ float As[16][64];
    __shared__ float Bs[16][64];
    int b  = blockIdx.z;
    int m0 = blockIdx.y * 64, n0 = blockIdx.x * 64;
    const float* A = g_xn + (size_t)b * NN * DD;
    const float* B = g_yn + (size_t)b * NN * DD;
    int t  = threadIdx.x;
    int tx = t & 15, ty = t >> 4;
    int lr = t >> 2, lk = (t & 3) << 2;
    float acc[4][4] = {};
    for (int k0 = 0; k0 < DD; k0 += 16) {
        float4 av = *(const float4*)(A + (size_t)(m0 + lr) * DD + k0 + lk);
        float4 bv = *(const float4*)(B + (size_t)(n0 + lr) * DD + k0 + lk);
        As[lk+0][lr] = av.x; As[lk+1][lr] = av.y; As[lk+2][lr] = av.z; As[lk+3][lr] = av.w;
        Bs[lk+0][lr] = bv.x; Bs[lk+1][lr] = bv.y; Bs[lk+2][lr] = bv.z; Bs[lk+3][lr] = bv.w;
        __syncthreads();
        #pragma unroll
        for (int k = 0; k < 16; k++) {
            float4 a  = *(const float4*)&As[k][ty << 2];
            float4 bb = *(const float4*)&Bs[k][tx << 2];
            acc[0][0] += a.x*bb.x; acc[0][1] += a.x*bb.y; acc[0][2] += a.x*bb.z; acc[0][3] += a.x*bb.w;
            acc[1][0] += a.y*bb.x; acc[1][1] += a.y*bb.y; acc[1][2] += a.y*bb.z; acc[1][3] += a.y*bb.w;
            acc[2][0] += a.z*bb.x; acc[2][1] += a.z*bb.y; acc[2][2] += a.z*bb.z; acc[2][3] += a.z*bb.w;
            acc[3][0] += a.w*bb.x; acc[3][1] += a.w*bb.y; acc[3][2] += a.w*bb.z; acc[3][3] += a.w*bb.w;
        }
        __syncthreads();
    }
    size_t base = (size_t)b * NN * NN;
    #pragma unroll
    for (int i = 0; i < 4; i++) {
        int row = m0 + (ty << 2) + i;
        #pragma unroll
        for (int j = 0; j < 4; j++) {
            int col = n0 + (tx << 2) + j;
            float c = 1.0f - acc[i][j];
            Cout[base + (size_t)row * NN + col] = c;
            g_E [base + (size_t)row * NN + col] = __expf(-INV_EPS * c);
        }
    }
}

// ---------------- 3) init state ----------------------------------------------
__global__ void init_kernel() {
    int i = blockIdx.x * blockDim.x + threadIdx.x;
    if (i < NB*NN) { g_u[i] = 1.f; g_v[i] = 1.f; g_p[i] = 1.f; g_q[i] = 1.f; g_w[i] = 1.f; }
}

// ---------------- 4) fused iteration: row half-step + column accumulation ----
// grid = NB*16, block 256 (8 warps); warp handles 4 rows (processed in 2x2
// interleaved pairs).  Lane owns columns [lane*16, lane*16+16):
//   rowsum_i = sum_j E_ij * w_j           (w = q*v, in registers)
//   u_i = MARG / (p_i * rowsum_i + TINY);  p_i *= u_i
//   colacc_j += E_ij * p_i(new)           (E still in registers)
// Per-block column partials -> g_colpart (deterministic, no float atomics).
__global__ void __launch_bounds__(256, 3) iter_kernel() {
    int b     = blockIdx.x >> 4;
    int chunk = blockIdx.x & 15;
    int t     = threadIdx.x;
    int warp  = t >> 5, lane = t & 31;
    size_t ebase = (size_t)b * NN * NN;

    // lane's w chunk (columns lane*16 .. lane*16+15), fixed for all rows
    const float4* W4 = (const float4*)(g_w + b * NN);
    float4 w0 = W4[lane*4+0], w1 = W4[lane*4+1], w2 = W4[lane*4+2], w3 = W4[lane*4+3];

    float4 ca0 = {0,0,0,0}, ca1 = {0,0,0,0}, ca2 = {0,0,0,0}, ca3 = {0,0,0,0};

    #pragma unroll
    for (int rp = 0; rp < 2; rp++) {
        int rowA = chunk*32 + warp*4 + rp*2;
        int rowB = rowA + 1;
        const float4* EA = (const float4*)(g_E + ebase + (size_t)rowA * NN);
        const float4* EB = (const float4*)(g_E + ebase + (size_t)rowB * NN);
        // issue all 8 loads up front (high MLP)
        float4 a0 = EA[lane*4+0], a1 = EA[lane*4+1], a2 = EA[lane*4+2], a3 = EA[lane*4+3];
        float4 b0 = EB[lane*4+0], b1 = EB[lane*4+1], b2 = EB[lane*4+2], b3 = EB[lane*4+3];

        // partial dots (4 independent chains each, then tree-combine)
        float sA0 = a0.x*w0.x + a0.y*w0.y + a0.z*w0.z + a0.w*w0.w;
        float sA1 = a1.x*w1.x + a1.y*w1.y + a1.z*w1.z + a1.w*w1.w;
        float sA2 = a2.x*w2.x + a2.y*w2.y + a2.z*w2.z + a2.w*w2.w;
        float sA3 = a3.x*w3.x + a3.y*w3.y + a3.z*w3.z + a3.w*w3.w;
        float sB0 = b0.x*w0.x + b0.y*w0.y + b0.z*w0.z + b0.w*w0.w;
        float sB1 = b1.x*w1.x + b1.y*w1.y + b1.z*w1.z + b1.w*w1.w;
        float sB2 = b2.x*w2.x + b2.y*w2.y + b2.z*w2.z + b2.w*w2.w;
        float sB3 = b3.x*w3.x + b3.y*w3.y + b3.z*w3.z + b3.w*w3.w;
        float sA = (sA0 + sA1) + (sA2 + sA3);
        float sB = (sB0 + sB1) + (sB2 + sB3);

        // two independent butterfly chains (overlap)
        #pragma unroll
        for (int o = 16; o; o >>= 1) {
            sA += __shfl_xor_sync(0xffffffffu, sA, o);
            sB += __shfl_xor_sync(0xffffffffu, sB, o);
        }

        // every lane computes p_new locally (broadcast load of g_p)
        float pA = g_p[b*NN + rowA];
        float pB = g_p[b*NN + rowB];
        float uA = MARG / (pA * sA + TINYF);
        float uB = MARG / (pB * sB + TINYF);
        float pnA = pA * uA;
        float pnB = pB * uB;
        if (lane == 0) {
            g_u[b*NN + rowA] = uA;  g_p[b*NN + rowA] = pnA;
            g_u[b*NN + rowB] = uB;  g_p[b*NN + rowB] = pnB;
        }

        // column accumulation with E still in registers
        ca0.x += a0.x*pnA + b0.x*pnB;  ca0.y += a0.y*pnA + b0.y*pnB;
        ca0.z += a0.z*pnA + b0.z*pnB;  ca0.w += a0.w*pnA + b0.w*pnB;
        ca1.x += a1.x*pnA + b1.x*pnB;  ca1.y += a1.y*pnA + b1.y*pnB;
        ca1.z += a1.z*pnA + b1.z*pnB;  ca1.w += a1.w*pnA + b1.w*pnB;
        ca2.x += a2.x*pnA + b2.x*pnB;  ca2.y += a2.y*pnA + b2.y*pnB;
        ca2.z += a2.z*pnA + b2.z*pnB;  ca2.w += a2.w*pnA + b2.w*pnB;
        ca3.x += a3.x*pnA + b3.x*pnB;  ca3.y += a3.y*pnA + b3.y*pnB;
        ca3.z += a3.z*pnA + b3.z*pnB;  ca3.w += a3.w*pnA + b3.w*pnB;
    }

    // cross-warp column reduce in smem, then one partial row per block
    __shared__ float cs[8][NN];
    float4* csr = (float4*)cs[warp];
    csr[lane*4+0] = ca0; csr[lane*4+1] = ca1; csr[lane*4+2] = ca2; csr[lane*4+3] = ca3;
    __syncthreads();
    #pragma unroll
    for (int k = 0; k < 2; k++) {
        int col = t + k*256;
        float s = 0.f;
        #pragma unroll
        for (int wv = 0; wv < 8; wv++) s += cs[wv][col];
        g_colpart[(size_t)blockIdx.x * NN + col] = s;
    }
}

// ---------------- 5) per-batch fixup: reduce col partials, update v/q/w ------
__global__ void fixup_kernel() {
    int b = blockIdx.x;
    int j = threadIdx.x;
    float s = 0.f;
    #pragma unroll
    for (int k = 0; k < 16; k++)
        s += g_colpart[(size_t)(b*16 + k) * NN + j];
    float q = g_q[b*NN + j];
    float v = MARG / (q * s + TINYF);
    float qn = q * v;
    g_v[b*NN + j] = v;
    g_q[b*NN + j] = qn;
    g_w[b*NN + j] = qn * v;
}

// ---------------- 6) pi = E * (u_i p_i) * (v_j q_j); cost partials -----------
__global__ void final_kernel(float* __restrict__ pi, const float* __restrict__ C) {
    int b     = blockIdx.x >> 4;
    int chunk = blockIdx.x & 15;
    __shared__ float svs[NN];
    __shared__ float red[256];
    int t = threadIdx.x;
    for (int j = t; j < NN; j += 256) svs[j] = g_v[b*NN + j] * g_q[b*NN + j];
    __syncthreads();
    int warp = t >> 5, lane = t & 31;
    size_t base = (size_t)b * NN * NN;
    float csum = 0.f;
    #pragma unroll
    for (int r = 0; r < 4; r++) {
        int row = chunk * 32 + warp * 4 + r;
        float su = g_u[b*NN + row] * g_p[b*NN + row];
        const float4* E4 = (const float4*)(g_E + base + (size_t)row * NN);
        const float4* C4 = (const float4*)(C   + base + (size_t)row * NN);
        float4*       P4 = (float4*)      (pi  + base + (size_t)row * NN);
        const float4* S4 = (const float4*)svs;
        #pragma unroll
        for (int c = 0; c < 4; c++) {
            int idx = lane * 4 + c;
            float4 e  = E4[idx];
            float4 s  = S4[idx];
            float4 cc = C4[idx];
            float4 pv;
            pv.x = e.x * su * s.x;
            pv.y = e.y * su * s.y;
            pv.z = e.z * su * s.z;
            pv.w = e.w * su * s.w;
            csum += pv.x*cc.x + pv.y*cc.y + pv.z*cc.z + pv.w*cc.w;
            P4[idx] = pv;
        }
    }
    red[t] = csum;
    __syncthreads();
    for (int o = 128; o; o >>= 1) {
        if (t < o) red[t] += red[t + o];
        __syncthreads();
    }
    if (t == 0) g_cpart[b * 16 + chunk] = red[0];
}

// ---------------- 7) reduce cost partials ------------------------------------
__global__ void cost_kernel(float* __restrict__ cost) {
    int b = threadIdx.x;
    if (b < NB) {
        float s = 0.f;
        #pragma unroll
        for (int c = 0; c < 16; c++) s += g_cpart[b * 16 + c];
        cost[b] = s;
    }
}

// ---------------- launch ------------------------------------------------------
extern "C" void kernel_launch(void* const* d_in, const int* in_sizes, int n_in,
                              void* d_out, int out_size) {
    const float* x = (const float*)d_in[0];
    const float* y = (const float*)d_in[1];
    float* out  = (float*)d_out;
    float* cost = out;
    float* pi   = out + NB;
    float* C    = out + NB + (size_t)NB * NN * NN;

    norm_kernel<<<4096, 256>>>(x, y);
    gemm_kernel<<<dim3(8, 8, NB), 256>>>(C);
    init_kernel<<<(NB * NN + 255) / 256, 256>>>();
    for (int it = 0; it < ITERS; it++) {
        iter_kernel<<<NB * 16, 256>>>();
        fixup_kernel<<<NB, NN>>>();
    }
    final_kernel<<<NB * 16, 256>>>(pi, C);
    cost_kernel<<<1, 32>>>(cost);
}

// round 4
// speedup vs baseline: 4.2373x; 2.2907x over previous
#include <cuda_runtime.h>
#include <cuda_bf16.h>
#include <math.h>

#define NB 32
#define NN 512
#define DD 256
#define INV_EPS 10.0f
#define TINYF 1e-16f
#define MARG (1.0f/512.0f)
#define ITERS 15
#define PGRID 128      // persistent grid: 4 blocks per batch
#define PTHREADS 512

// ---------------- scratch (static __device__; no allocations) ----------------
static __device__ float g_xn[(size_t)NB*NN*DD];          // 16 MB normalized x
static __device__ float g_yn[(size_t)NB*NN*DD];          // 16 MB normalized y
static __device__ float g_E [(size_t)NB*NN*NN];          // 32 MB  E = exp(-C/eps) fp32
static __device__ float g_colpart[2][PGRID][NN];         // double-buffered col partials
static __device__ float g_cpart[PGRID];                  // per-block cost partials
static __device__ int   g_bar[NB];                       // per-batch arrival counters

// ---------------- 1) row-normalize x and y -----------------------------------
__global__ void norm_kernel(const float* __restrict__ x, const float* __restrict__ y) {
    int gw   = (blockIdx.x * blockDim.x + threadIdx.x) >> 5;
    int lane = threadIdx.x & 31;
    const float* src; float* dst; int row;
    if (gw < NB*NN) { src = x; dst = g_xn; row = gw; }
    else            { src = y; dst = g_yn; row = gw - NB*NN; }
    const float4* s4 = (const float4*)(src + (size_t)row * DD);
    float4 a = s4[lane];
    float4 b = s4[lane + 32];
    float ss = a.x*a.x + a.y*a.y + a.z*a.z + a.w*a.w
             + b.x*b.x + b.y*b.y + b.z*b.z + b.w*b.w;
    #pragma unroll
    for (int o = 16; o; o >>= 1) ss += __shfl_xor_sync(0xffffffffu, ss, o);
    float r = rsqrtf(ss);
    a.x*=r; a.y*=r; a.z*=r; a.w*=r;
    b.x*=r; b.y*=r; b.z*=r; b.w*=r;
    float4* d4 = (float4*)(dst + (size_t)row * DD);
    d4[lane]      = a;
    d4[lane + 32] = b;
}

// ---------------- 2) tf32 tensor-core GEMM: C = 1 - xn*yn^T ; E = exp(-10C) --
// BM=128, BN=64, BK=32; 256 threads = 8 warps (4m x 2n); warp tile 32x32;
// per warp: 2 m16-tiles x 4 n8-tiles of mma.m16n8k8.tf32
__device__ __forceinline__ unsigned f2tf32(float f) {
    unsigned r;
    asm("cvt.rna.tf32.f32 %0, %1;" : "=r"(r) : "f"(f));
    return r;
}

__global__ void __launch_bounds__(256) gemm_kernel(float* __restrict__ Cout) {
    __shared__ float As[128][36];
    __shared__ float Bs[64][36];
    int b  = blockIdx.z;
    int m0 = blockIdx.y * 128, n0 = blockIdx.x * 64;
    const float* A = g_xn + (size_t)b * NN * DD;
    const float* B = g_yn + (size_t)b * NN * DD;
    int t = threadIdx.x, lane = t & 31, warp = t >> 5;
    int wm = (warp >> 1) * 32;      // warp m offset (0,32,64,96)
    int wn = (warp & 1) * 32;       // warp n offset (0,32)
    int lr = t >> 3;                // 0..31
    int lc = (t & 7) * 4;           // 0..28

    float acc[2][4][4];
    #pragma unroll
    for (int i=0;i<2;i++)
        #pragma unroll
        for (int j=0;j<4;j++)
            #pragma unroll
            for (int k=0;k<4;k++) acc[i][j][k] = 0.f;

    for (int k0 = 0; k0 < DD; k0 += 32) {
        #pragma unroll
        for (int i = 0; i < 4; i++) {
            float4 v = *(const float4*)(A + (size_t)(m0 + lr + 32*i) * DD + k0 + lc);
            float4 w;
            w.x = __uint_as_float(f2tf32(v.x)); w.y = __uint_as_float(f2tf32(v.y));
            w.z = __uint_as_float(f2tf32(v.z)); w.w = __uint_as_float(f2tf32(v.w));
            *(float4*)&As[lr + 32*i][lc] = w;
        }
        #pragma unroll
        for (int i = 0; i < 2; i++) {
            float4 v = *(const float4*)(B + (size_t)(n0 + lr + 32*i) * DD + k0 + lc);
            float4 w;
            w.x = __uint_as_float(f2tf32(v.x)); w.y = __uint_as_float(f2tf32(v.y));
            w.z = __uint_as_float(f2tf32(v.z)); w.w = __uint_as_float(f2tf32(v.w));
            *(float4*)&Bs[lr + 32*i][lc] = w;
        }
        __syncthreads();
        #pragma unroll
        for (int s = 0; s < 4; s++) {
            int kk = s * 8;
            int kc = kk + (lane & 3);
            unsigned bf[4][2];
            #pragma unroll
            for (int nt = 0; nt < 4; nt++) {
                int nb = wn + nt*8 + (lane >> 2);
                bf[nt][0] = __float_as_uint(Bs[nb][kc]);
                bf[nt][1] = __float_as_uint(Bs[nb][kc + 4]);
            }
            #pragma unroll
            for (int mt = 0; mt < 2; mt++) {
                int ma = wm + mt*16 + (lane >> 2);
                unsigned a0 = __float_as_uint(As[ma    ][kc]);
                unsigned a1 = __float_as_uint(As[ma + 8][kc]);
                unsigned a2 = __float_as_uint(As[ma    ][kc + 4]);
                unsigned a3 = __float_as_uint(As[ma + 8][kc + 4]);
                #pragma unroll
                for (int nt = 0; nt < 4; nt++) {
                    asm volatile(
                        "mma.sync.aligned.m16n8k8.row.col.f32.tf32.tf32.f32 "
                        "{%0,%1,%2,%3}, {%4,%5,%6,%7}, {%8,%9}, {%0,%1,%2,%3};"
                        : "+f"(acc[mt][nt][0]), "+f"(acc[mt][nt][1]),
                          "+f"(acc[mt][nt][2]), "+f"(acc[mt][nt][3])
                        : "r"(a0), "r"(a1), "r"(a2), "r"(a3),
                          "r"(bf[nt][0]), "r"(bf[nt][1]));
                }
            }
        }
        __syncthreads();
    }

    size_t base = (size_t)b * NN * NN;
    #pragma unroll
    for (int mt = 0; mt < 2; mt++) {
        #pragma unroll
        for (int nt = 0; nt < 4; nt++) {
            int m = m0 + wm + mt*16 + (lane >> 2);
            int n = n0 + wn + nt*8 + (lane & 3)*2;
            float c0 = 1.0f - acc[mt][nt][0];
            float c1 = 1.0f - acc[mt][nt][1];
            float c2 = 1.0f - acc[mt][nt][2];
            float c3 = 1.0f - acc[mt][nt][3];
            *(float2*)&Cout[base + (size_t)m*NN + n]     = make_float2(c0, c1);
            *(float2*)&g_E [base + (size_t)m*NN + n]     = make_float2(__expf(-INV_EPS*c0), __expf(-INV_EPS*c1));
            *(float2*)&Cout[base + (size_t)(m+8)*NN + n] = make_float2(c2, c3);
            *(float2*)&g_E [base + (size_t)(m+8)*NN + n] = make_float2(__expf(-INV_EPS*c2), __expf(-INV_EPS*c3));
        }
    }
}

// ---------------- 3) reset per-batch barriers --------------------------------
__global__ void init_kernel() {
    if (threadIdx.x < NB) g_bar[threadIdx.x] = 0;
}

// ---------------- 4) persistent Sinkhorn kernel ------------------------------
// 128 blocks (all resident), block g handles batch b=g/4, rows [rc*128, +128).
// E tile cached in smem as bf16 (128KB). 15 iterations with per-batch
// 4-block barrier per iteration. Final pi/cost pass folded in (uses fp32 E).
#define SMEM_EBF   0
#define SMEM_COLP  (131072)
#define SMEM_W     (131072 + 32768)
#define SMEM_Q     (SMEM_W + 2048)
#define SMEM_P     (SMEM_Q + 2048)
#define SMEM_SU    (SMEM_P + 512)
#define SMEM_TOTAL (SMEM_SU + 512 + 64)

__global__ void __launch_bounds__(PTHREADS, 1) sink_kernel(float* __restrict__ pi,
                                                           const float* __restrict__ C) {
    extern __shared__ unsigned char smraw[];
    unsigned* Eu  = (unsigned*)(smraw + SMEM_EBF);       // [128][256] words (2 bf16/word)
    float* colp   = (float*)(smraw + SMEM_COLP);         // [16][512]
    float* w      = (float*)(smraw + SMEM_W);            // [512]
    float* q      = (float*)(smraw + SMEM_Q);            // [512]
    float* p      = (float*)(smraw + SMEM_P);            // [128]
    float* su     = (float*)(smraw + SMEM_SU);           // [128]

    int g = blockIdx.x, b = g >> 2, rc = g & 3;
    int row0 = rc * 128;
    int t = threadIdx.x, warp = t >> 5, lane = t & 31;
    const float* Eg = g_E + ((size_t)b * NN + row0) * NN;

    // prologue: fp32 E -> bf16 smem
    for (int i = t; i < 128*512/4; i += PTHREADS) {
        float4 v = *(const float4*)(Eg + (size_t)i * 4);
        __nv_bfloat162 lo = __floats2bfloat162_rn(v.x, v.y);
        __nv_bfloat162 hi = __floats2bfloat162_rn(v.z, v.w);
        uint2 pk;
        pk.x = *(unsigned*)&lo;
        pk.y = *(unsigned*)&hi;
        *(uint2*)&Eu[i*2] = pk;
    }
    w[t < 512 ? t : 0] = 1.f;   // t always < 512
    q[t] = 1.f;
    if (t < 128) { p[t] = 1.f; }
    __syncthreads();

    for (int it = 0; it < ITERS; it++) {
        // lane owns column pairs: cols {2*lane + 64k, 2*lane+64k+1}, k=0..7
        float wreg[16];
        #pragma unroll
        for (int k = 0; k < 8; k++) {
            wreg[2*k]   = w[2*lane + 64*k];
            wreg[2*k+1] = w[2*lane + 64*k + 1];
        }
        float colacc[16];
        #pragma unroll
        for (int i = 0; i < 16; i++) colacc[i] = 0.f;

        #pragma unroll 2
        for (int r = 0; r < 8; r++) {
            int row = warp * 8 + r;
            float e[16];
            #pragma unroll
            for (int k = 0; k < 8; k++) {
                unsigned wd = Eu[row * 256 + lane + 32*k];
                e[2*k]   = __uint_as_float(wd << 16);          // low bf16 -> f32
                e[2*k+1] = __uint_as_float(wd & 0xffff0000u);  // high bf16 -> f32
            }
            float d0=0.f, d1=0.f, d2=0.f, d3=0.f;
            #pragma unroll
            for (int k = 0; k < 4; k++) {
                d0 += e[4*k+0] * wreg[4*k+0];
                d1 += e[4*k+1] * wreg[4*k+1];
                d2 += e[4*k+2] * wreg[4*k+2];
                d3 += e[4*k+3] * wreg[4*k+3];
            }
            float d = (d0 + d1) + (d2 + d3);
            #pragma unroll
            for (int o = 16; o; o >>= 1) d += __shfl_xor_sync(0xffffffffu, d, o);
            float pold = p[row];
            float un = MARG / (pold * d + TINYF);
            float pn = pold * un;
            if (lane == 0) {
                p[row] = pn;
                if (it == ITERS - 1) su[row] = un * pn;   // u_final * p_final
            }
            #pragma unroll
            for (int i = 0; i < 16; i++) colacc[i] += e[i] * pn;
        }
        // stage per-warp column partials
        #pragma unroll
        for (int k = 0; k < 8; k++) {
            *(float2*)&colp[warp * 512 + 2*lane + 64*k] =
                make_float2(colacc[2*k], colacc[2*k+1]);
        }
        __syncthreads();
        // block-level column reduce: thread t owns column t
        {
            float s = 0.f;
            #pragma unroll
            for (int wv = 0; wv < 16; wv++) s += colp[wv * 512 + t];
            g_colpart[it & 1][g][t] = s;
        }
        __threadfence();
        __syncthreads();
        if (t == 0) {
            atomicAdd(&g_bar[b], 1);
            int target = 4 * (it + 1);
            while (atomicAdd(&g_bar[b], 0) < target) __nanosleep(64);
        }
        __syncthreads();
        __threadfence();
        // column update (each block computes full q,w redundantly -> deterministic)
        {
            const float* cp = &g_colpart[it & 1][0][0];
            int b4 = b * 4;
            float tot = __ldcg(&cp[(b4+0)*NN + t]) + __ldcg(&cp[(b4+1)*NN + t])
                      + __ldcg(&cp[(b4+2)*NN + t]) + __ldcg(&cp[(b4+3)*NN + t]);
            float qold = q[t];
            float v = MARG / (qold * tot + TINYF);
            float qn = qold * v;
            q[t] = qn;
            w[t] = qn * v;      // w = v * q_final  (== svs for the final pass)
        }
        __syncthreads();
    }

    // final: pi = Efp32 * su[row] * w[col]; cost partial
    size_t base = ((size_t)b * NN + row0) * NN;
    float csum = 0.f;
    for (int r = 0; r < 8; r++) {
        int row = warp * 8 + r;
        float s_u = su[row];
        const float4* E4 = (const float4*)(g_E + base + (size_t)row * NN);
        const float4* C4 = (const float4*)(C   + base + (size_t)row * NN);
        float4*       P4 = (float4*)      (pi  + base + (size_t)row * NN);
        #pragma unroll
        for (int k = 0; k < 4; k++) {
            int idx = lane + 32*k;
            float4 e  = E4[idx];
            float4 cc = C4[idx];
            int c0 = idx * 4;
            float4 pv;
            pv.x = e.x * s_u * w[c0+0];
            pv.y = e.y * s_u * w[c0+1];
            pv.z = e.z * s_u * w[c0+2];
            pv.w = e.w * s_u * w[c0+3];
            csum += pv.x*cc.x + pv.y*cc.y + pv.z*cc.z + pv.w*cc.w;
            P4[idx] = pv;
        }
    }
    #pragma unroll
    for (int o = 16; o; o >>= 1) csum += __shfl_xor_sync(0xffffffffu, csum, o);
    __shared__ float cred[16];
    if (lane == 0) cred[warp] = csum;
    __syncthreads();
    if (t == 0) {
        float s = 0.f;
        #pragma unroll
        for (int i = 0; i < 16; i++) s += cred[i];
        g_cpart[g] = s;
    }
}

// ---------------- 5) reduce cost partials ------------------------------------
__global__ void cost_kernel(float* __restrict__ cost) {
    int b = threadIdx.x;
    if (b < NB) {
        float s = 0.f;
        #pragma unroll
        for (int k = 0; k < 4; k++) s += g_cpart[b*4 + k];
        cost[b] = s;
    }
}

// ---------------- launch ------------------------------------------------------
extern "C" void kernel_launch(void* const* d_in, const int* in_sizes, int n_in,
                              void* d_out, int out_size) {
    const float* x = (const float*)d_in[0];
    const float* y = (const float*)d_in[1];
    float* out  = (float*)d_out;
    float* cost = out;
    float* pi   = out + NB;
    float* C    = out + NB + (size_t)NB * NN * NN;

    static int smem_set = 0;
    if (!smem_set) {
        cudaFuncSetAttribute(sink_kernel,
                             cudaFuncAttributeMaxDynamicSharedMemorySize, SMEM_TOTAL);
        smem_set = 1;
    }

    norm_kernel<<<4096, 256>>>(x, y);
    gemm_kernel<<<dim3(8, 4, NB), 256>>>(C);
    init_kernel<<<1, 32>>>();
    sink_kernel<<<PGRID, PTHREADS, SMEM_TOTAL>>>(pi, C);
    cost_kernel<<<1, 32>>>(cost);
}